// round 1
// baseline (speedup 1.0000x reference)
#include <cuda_runtime.h>
#include <cstdint>

// Problem constants
#define NB     32      // batch rows per CTA
#define TPB    256     // threads per CTA
#define NCTA   128     // 128 * 32 = 4096 batch
#define HD     128     // hidden units H
#define DD     64      // latent dim D
#define G4     512     // 4*H gate width
#define KT     16      // k-tile rows for weight streaming
#define TWARM  50
#define NSTEPS 149     // 50 warmup + 99 AR lstm steps
#define TOUT   100

// ---------------- async copy helpers ----------------
__device__ __forceinline__ void cp_async16(void* dst, const void* src) {
    unsigned d = (unsigned)__cvta_generic_to_shared(dst);
    asm volatile("cp.async.cg.shared.global [%0], [%1], 16;\n" :: "r"(d), "l"(src));
}
__device__ __forceinline__ void cp_commit() { asm volatile("cp.async.commit_group;\n" ::); }
__device__ __forceinline__ void cp_wait1()  { asm volatile("cp.async.wait_group 1;\n" ::: "memory"); }
__device__ __forceinline__ void cp_wait0()  { asm volatile("cp.async.wait_group 0;\n" ::: "memory"); }

// ---------------- fast activations (MUFU-based, ~1e-6 rel err) ----------------
__device__ __forceinline__ float sig_f(float x) {
    return __fdividef(1.0f, 1.0f + __expf(-x));
}
__device__ __forceinline__ float tanh_f(float x) {
    return 1.0f - __fdividef(2.0f, __expf(2.0f * x) + 1.0f);
}

// Load one KT x G4 fp32 weight tile (contiguous 32KB) global -> smem via cp.async
__device__ __forceinline__ void load_tile(float* buf, const float* __restrict__ src, int tid) {
#pragma unroll
    for (int i = 0; i < (KT * G4) / (4 * TPB); ++i) {   // 8 x 16B per thread
        int idx = (i * TPB + tid) * 4;
        cp_async16(buf + idx, src + idx);
    }
}

// acc[4][16] += A[NB x astride](cols 0..NT*KT-1) * W(NT*KT x 512)
// thread (tb,tj): rows tb*4..tb*4+3, cols { g*128 + tj*4 + jj : g,jj in 0..3 }
__device__ __forceinline__ void gemm_part(
    float acc[4][16], const float* __restrict__ As, int astride,
    const float* __restrict__ Wg, int NT,
    float* wbuf, int tid, int tb, int tj)
{
    load_tile(wbuf, Wg, tid);
    cp_commit();
#pragma unroll 1
    for (int t = 0; t < NT; ++t) {
        if (t + 1 < NT) {
            load_tile(wbuf + ((t + 1) & 1) * (KT * G4), Wg + (t + 1) * (KT * G4), tid);
            cp_commit();
            cp_wait1();
        } else {
            cp_wait0();
        }
        __syncthreads();
        const float* wt = wbuf + (t & 1) * (KT * G4);
        const int k0 = t * KT;
#pragma unroll
        for (int kk4 = 0; kk4 < KT; kk4 += 4) {
            float a[4][4];
#pragma unroll
            for (int i = 0; i < 4; ++i) {
                float4 av = *(const float4*)&As[(tb * 4 + i) * astride + k0 + kk4];
                a[i][0] = av.x; a[i][1] = av.y; a[i][2] = av.z; a[i][3] = av.w;
            }
#pragma unroll
            for (int u = 0; u < 4; ++u) {
                float wv[16];
#pragma unroll
                for (int g = 0; g < 4; ++g) {
                    float4 w4 = *(const float4*)&wt[(kk4 + u) * G4 + g * HD + tj * 4];
                    wv[g * 4 + 0] = w4.x; wv[g * 4 + 1] = w4.y;
                    wv[g * 4 + 2] = w4.z; wv[g * 4 + 3] = w4.w;
                }
#pragma unroll
                for (int i = 0; i < 4; ++i)
#pragma unroll
                    for (int c = 0; c < 16; ++c)
                        acc[i][c] = fmaf(a[i][u], wv[c], acc[i][c]);
            }
        }
        __syncthreads();
    }
}

extern "C" __global__ void __launch_bounds__(TPB, 1)
lstm_rollout_kernel(const float* __restrict__ x,
                    const float* __restrict__ Wk0, const float* __restrict__ Wr0, const float* __restrict__ b0,
                    const float* __restrict__ Wk1, const float* __restrict__ Wr1, const float* __restrict__ b1,
                    const float* __restrict__ Wd,  const float* __restrict__ bd,
                    float* __restrict__ out)
{
    extern __shared__ float sm[];
    float* wbuf = sm;                        // [2][KT*G4]    16384 f
    float* xs   = wbuf + 2 * KT * G4;        // [NB][DD]       2048 f  (input / pred)
    float* h0s  = xs   + NB * DD;            // [NB][HD]       4096 f
    float* h1s  = h0s  + NB * HD;            // [NB][HD]       4096 f
    float* wds  = h1s  + NB * HD;            // [HD][DD]       8192 f  (resident Wd)
    float* b0s  = wds  + HD * DD;            // [G4]
    float* b1s  = b0s  + G4;                 // [G4]
    float* bds  = b1s  + G4;                 // [DD]

    const int tid = threadIdx.x;
    const int tj  = tid & 31;
    const int tb  = tid >> 5;
    const int gb0 = blockIdx.x * NB;

    // resident weights / biases, zero states
    for (int i = tid; i < HD * DD; i += TPB) wds[i] = Wd[i];
    for (int i = tid; i < G4; i += TPB) { b0s[i] = b0[i]; b1s[i] = b1[i]; }
    if (tid < DD) bds[tid] = bd[tid];
    for (int i = tid; i < NB * HD; i += TPB) { h0s[i] = 0.0f; h1s[i] = 0.0f; }

    float c0r[4][4], c1r[4][4];
#pragma unroll
    for (int i = 0; i < 4; ++i)
#pragma unroll
        for (int j = 0; j < 4; ++j) { c0r[i][j] = 0.0f; c1r[i][j] = 0.0f; }
    __syncthreads();

#pragma unroll 1
    for (int step = 0; step < NSTEPS; ++step) {
        // ---- input: warmup reads x[:, step, :]; AR phase reuses xs (= previous pred)
        if (step < TWARM) {
#pragma unroll
            for (int i = 0; i < (NB * DD) / TPB; ++i) {
                int idx = i * TPB + tid;
                int b = idx >> 6, d = idx & 63;
                xs[idx] = x[((size_t)(gb0 + b) * TWARM + step) * DD + d];
            }
            __syncthreads();
        }

        float acc[4][16];

        // ================= layer 0 =================
        {
            float bv[16];
#pragma unroll
            for (int g = 0; g < 4; ++g)
#pragma unroll
                for (int jj = 0; jj < 4; ++jj)
                    bv[g * 4 + jj] = b0s[g * HD + tj * 4 + jj];
#pragma unroll
            for (int i = 0; i < 4; ++i)
#pragma unroll
                for (int c = 0; c < 16; ++c) acc[i][c] = bv[c];
        }
        gemm_part(acc, xs,  DD, Wk0, DD / KT, wbuf, tid, tb, tj);   // 4 tiles
        gemm_part(acc, h0s, HD, Wr0, HD / KT, wbuf, tid, tb, tj);   // 8 tiles
        {
            float hst[4][4];
#pragma unroll
            for (int i = 0; i < 4; ++i)
#pragma unroll
                for (int jj = 0; jj < 4; ++jj) {
                    float ii = sig_f (acc[i][0  + jj]);
                    float ff = sig_f (acc[i][4  + jj]);
                    float gg = tanh_f(acc[i][8  + jj]);
                    float oo = sig_f (acc[i][12 + jj]);
                    float cn = fmaf(ff, c0r[i][jj], ii * gg);
                    c0r[i][jj] = cn;
                    hst[i][jj] = oo * tanh_f(cn);
                }
#pragma unroll
            for (int i = 0; i < 4; ++i)
                *(float4*)&h0s[(tb * 4 + i) * HD + tj * 4] =
                    make_float4(hst[i][0], hst[i][1], hst[i][2], hst[i][3]);
        }
        __syncthreads();

        // ================= layer 1 =================
        {
            float bv[16];
#pragma unroll
            for (int g = 0; g < 4; ++g)
#pragma unroll
                for (int jj = 0; jj < 4; ++jj)
                    bv[g * 4 + jj] = b1s[g * HD + tj * 4 + jj];
#pragma unroll
            for (int i = 0; i < 4; ++i)
#pragma unroll
                for (int c = 0; c < 16; ++c) acc[i][c] = bv[c];
        }
        gemm_part(acc, h0s, HD, Wk1, HD / KT, wbuf, tid, tb, tj);   // 8 tiles
        gemm_part(acc, h1s, HD, Wr1, HD / KT, wbuf, tid, tb, tj);   // 8 tiles
        {
            float hst[4][4];
#pragma unroll
            for (int i = 0; i < 4; ++i)
#pragma unroll
                for (int jj = 0; jj < 4; ++jj) {
                    float ii = sig_f (acc[i][0  + jj]);
                    float ff = sig_f (acc[i][4  + jj]);
                    float gg = tanh_f(acc[i][8  + jj]);
                    float oo = sig_f (acc[i][12 + jj]);
                    float cn = fmaf(ff, c1r[i][jj], ii * gg);
                    c1r[i][jj] = cn;
                    hst[i][jj] = oo * tanh_f(cn);
                }
#pragma unroll
            for (int i = 0; i < 4; ++i)
                *(float4*)&h1s[(tb * 4 + i) * HD + tj * 4] =
                    make_float4(hst[i][0], hst[i][1], hst[i][2], hst[i][3]);
        }
        __syncthreads();

        // ============ dense decode: pred = h1 @ Wd + bd (steps >= 49) ============
        if (step >= TWARM - 1) {
            const int s = step - (TWARM - 1);         // 0..99
            float d0[4], d1[4];
            const float bw0 = bds[tj * 2], bw1 = bds[tj * 2 + 1];
#pragma unroll
            for (int i = 0; i < 4; ++i) { d0[i] = bw0; d1[i] = bw1; }
#pragma unroll
            for (int k4 = 0; k4 < HD; k4 += 4) {
                float a[4][4];
#pragma unroll
                for (int i = 0; i < 4; ++i) {
                    float4 av = *(const float4*)&h1s[(tb * 4 + i) * HD + k4];
                    a[i][0] = av.x; a[i][1] = av.y; a[i][2] = av.z; a[i][3] = av.w;
                }
#pragma unroll
                for (int u = 0; u < 4; ++u) {
                    float2 w2 = *(const float2*)&wds[(k4 + u) * DD + tj * 2];
#pragma unroll
                    for (int i = 0; i < 4; ++i) {
                        d0[i] = fmaf(a[i][u], w2.x, d0[i]);
                        d1[i] = fmaf(a[i][u], w2.y, d1[i]);
                    }
                }
            }
#pragma unroll
            for (int i = 0; i < 4; ++i) {
                float2 p = make_float2(d0[i], d1[i]);
                *(float2*)&xs[(tb * 4 + i) * DD + tj * 2] = p;            // feed next step
                *(float2*)&out[((size_t)(gb0 + tb * 4 + i) * TOUT + s) * DD + tj * 2] = p;
            }
            __syncthreads();
        }
    }
}

extern "C" void kernel_launch(void* const* d_in, const int* in_sizes, int n_in,
                              void* d_out, int out_size)
{
    const float* x   = (const float*)d_in[0];
    const float* Wk0 = (const float*)d_in[1];
    const float* Wr0 = (const float*)d_in[2];
    const float* b0  = (const float*)d_in[3];
    const float* Wk1 = (const float*)d_in[4];
    const float* Wr1 = (const float*)d_in[5];
    const float* b1  = (const float*)d_in[6];
    const float* Wd  = (const float*)d_in[7];
    const float* bd  = (const float*)d_in[8];

    size_t smem = (size_t)(2 * KT * G4 + NB * DD + 2 * NB * HD + HD * DD + 2 * G4 + DD) * sizeof(float);
    cudaFuncSetAttribute(lstm_rollout_kernel,
                         cudaFuncAttributeMaxDynamicSharedMemorySize, (int)smem);
    lstm_rollout_kernel<<<NCTA, TPB, smem>>>(x, Wk0, Wr0, b0, Wk1, Wr1, b1, Wd, bd,
                                             (float*)d_out);
}